// round 3
// baseline (speedup 1.0000x reference)
#include <cuda_runtime.h>
#include <math.h>
#include <stdint.h>

#define Vn 65536
#define En 262144
#define Gn 2048
#define NPG 32
#define H 200
#define DEG 4
#define NODE_IN 74
#define EDGE_IN 12
#define NLAYERS 5
#define TT 2
#define H3 600
#define H2 400

#define KT 25           // k-tiles of 8 (K=200)
#define NT 25           // n-tiles of 8 (N=200)
#define MB 64           // rows per block (2 graphs)
#define AGG_S 204       // padded stride for s_agg

// ---------------- device scratch ----------------
__device__ float g_h[Vn * H];        // node hidden states [V,H]
__device__ float g_eh[En * H];       // edge embeddings   [E,H]
__device__ float g_gf[Gn * H];       // graph features [G,H]
__device__ float g_a[Vn];            // readout attention per node
__device__ float g_hbar[Gn * H];     // sum_v a_v * h_v per graph
__device__ float g_ctx[Gn * H];      // elu(hbar @ prW + prb)
__device__ float g_gi[Gn * H3];      // GRU input gates
__device__ float g_gh[Gn * H3];      // GRU hidden gates
__device__ float g_WihT[TT][H * H3];
__device__ float g_WhhT[TT][H * H3];
// prepacked gnn_W fragments: [layer][kt][nt][lane] = (bhi0, bhi1, blo0, blo1)
__device__ uint4 g_Bpack[NLAYERS * KT * NT * 32];

// ---------------- tf32 helpers ----------------
__device__ __forceinline__ uint32_t f2tf32(float f) {
    uint32_t r;
    asm("cvt.rna.tf32.f32 %0, %1;" : "=r"(r) : "f"(f));
    return r;
}
__device__ __forceinline__ void mma_tf32(float* c, const uint32_t* a,
                                         uint32_t b0, uint32_t b1) {
    asm volatile(
        "mma.sync.aligned.m16n8k8.row.col.f32.tf32.tf32.f32 "
        "{%0,%1,%2,%3}, {%4,%5,%6,%7}, {%8,%9}, {%0,%1,%2,%3};"
        : "+f"(c[0]), "+f"(c[1]), "+f"(c[2]), "+f"(c[3])
        : "r"(a[0]), "r"(a[1]), "r"(a[2]), "r"(a[3]), "r"(b0), "r"(b1));
}

// ---------------- prepack gnn weights into tf32 hi/lo fragment order ----------------
__global__ void k_prep(const float* __restrict__ gnn_W) {
    int idx = blockIdx.x * blockDim.x + threadIdx.x;
    if (idx >= NLAYERS * KT * NT * 32) return;
    int lane = idx & 31;
    int r = idx >> 5;
    int nt = r % NT;
    int r2 = r / NT;
    int kt = r2 % KT;
    int l = r2 / KT;
    int k0 = kt * 8 + (lane & 3);
    int n = nt * 8 + (lane >> 2);
    float w0 = gnn_W[l * H * H + k0 * H + n];
    float w1 = gnn_W[l * H * H + (k0 + 4) * H + n];
    uint32_t hi0 = f2tf32(w0);
    uint32_t hi1 = f2tf32(w1);
    uint32_t lo0 = f2tf32(w0 - __uint_as_float(hi0));
    uint32_t lo1 = f2tf32(w1 - __uint_as_float(hi1));
    uint4 p;
    p.x = hi0; p.y = hi1; p.z = lo0; p.w = lo1;
    g_Bpack[idx] = p;
}

// ---------------- transpose GRU weights ----------------
__global__ void k_transpose(const float* __restrict__ W_ih,
                            const float* __restrict__ W_hh) {
    int idx = blockIdx.x * blockDim.x + threadIdx.x;
    if (idx < TT * H3 * H) {
        int t = idx / (H3 * H);
        int r = idx - t * (H3 * H);
        int j = r / H, k = r - j * H;
        g_WihT[t][k * H3 + j] = W_ih[idx];
        g_WhhT[t][k * H3 + j] = W_hh[idx];
    }
}

// ---------------- node embedding ----------------
__global__ __launch_bounds__(200) void k_node_embed(const float* __restrict__ nf,
                                                    const float* __restrict__ W,
                                                    const float* __restrict__ b) {
    __shared__ float s[32][NODE_IN];
    int v0 = blockIdx.x * 32;
    int tid = threadIdx.x;
    for (int i = tid; i < 32 * NODE_IN; i += 200) {
        int r = i / NODE_IN, k = i - r * NODE_IN;
        s[r][k] = nf[(v0 + r) * NODE_IN + k];
    }
    __syncthreads();
    int c = tid;
    float acc[32];
#pragma unroll
    for (int r = 0; r < 32; r++) acc[r] = 0.f;
    for (int k = 0; k < NODE_IN; k++) {
        float w = W[k * H + c];
#pragma unroll
        for (int r = 0; r < 32; r++) acc[r] += s[r][k] * w;
    }
    float bb = b[c];
#pragma unroll
    for (int r = 0; r < 32; r++) g_h[(v0 + r) * H + c] = acc[r] + bb;
}

// ---------------- edge embedding ----------------
__global__ __launch_bounds__(200) void k_edge_embed(const float* __restrict__ ef,
                                                    const float* __restrict__ W,
                                                    const float* __restrict__ b) {
    __shared__ float s[32][EDGE_IN];
    int e0 = blockIdx.x * 32;
    int tid = threadIdx.x;
    for (int i = tid; i < 32 * EDGE_IN; i += 200) {
        int r = i / EDGE_IN, k = i - r * EDGE_IN;
        s[r][k] = ef[(e0 + r) * EDGE_IN + k];
    }
    __syncthreads();
    int c = tid;
    float acc[32];
#pragma unroll
    for (int r = 0; r < 32; r++) acc[r] = 0.f;
    for (int k = 0; k < EDGE_IN; k++) {
        float w = W[k * H + c];
#pragma unroll
        for (int r = 0; r < 32; r++) acc[r] += s[r][k] * w;
    }
    float bb = b[c];
#pragma unroll
    for (int r = 0; r < 32; r++) g_eh[(e0 + r) * H + c] = acc[r] + bb;
}

// ---------------- fused layer: edge-softmax agg + tf32 tensor-core update ----------------
// block = 64 nodes (2 graphs), 128 threads (4 warps, warp w -> rows [16w,16w+16))
__global__ __launch_bounds__(128, 2) void k_layer(const int* __restrict__ src,
                                                  const float* __restrict__ bias,
                                                  int layer) {
    extern __shared__ float smem[];
    float* s_h = smem;                       // [64][200]
    float* s_agg = s_h + MB * H;             // [64][204]
    int* s_src = (int*)(s_agg + MB * AGG_S); // [256]
    float* s_bias = (float*)(s_src + MB * DEG);

    int tid = threadIdx.x;
    int b = blockIdx.x;
    int vbase = b * MB;

    // phase 1: stage h, src, bias
    {
        const float4* gsrc = (const float4*)(g_h + vbase * H);
        float4* dst = (float4*)s_h;
#pragma unroll
        for (int i = 0; i < (MB * H / 4) / 128; i++) dst[tid + i * 128] = gsrc[tid + i * 128];
        {
            int2 sp = ((const int2*)(src + b * MB * DEG))[tid];
            s_src[tid * 2] = sp.x - vbase;
            s_src[tid * 2 + 1] = sp.y - vbase;
        }
        for (int i = tid; i < H; i += 128) s_bias[i] = bias[i];   // FIX: full coverage
    }
    __syncthreads();

    // phase 2: per-element edge softmax + aggregation -> s_agg
    {
        const float* ehb = g_eh + (size_t)b * (MB * DEG) * H;
        for (int i = tid; i < MB * H; i += 128) {
            int v = i / H;
            int k = i - v * H;
            int e0 = v * DEG;
            float m0 = s_h[s_src[e0 + 0] * H + k] + __ldg(&ehb[(e0 + 0) * H + k]);
            float m1 = s_h[s_src[e0 + 1] * H + k] + __ldg(&ehb[(e0 + 1) * H + k]);
            float m2 = s_h[s_src[e0 + 2] * H + k] + __ldg(&ehb[(e0 + 2) * H + k]);
            float m3 = s_h[s_src[e0 + 3] * H + k] + __ldg(&ehb[(e0 + 3) * H + k]);
            float mx = fmaxf(fmaxf(m0, m1), fmaxf(m2, m3));
            float e0x = __expf(m0 - mx), e1x = __expf(m1 - mx);
            float e2x = __expf(m2 - mx), e3x = __expf(m3 - mx);
            float den = e0x + e1x + e2x + e3x;
            float agg = m0 * e0x + m1 * e1x + m2 * e2x + m3 * e3x;
            s_agg[v * AGG_S + k] = agg / den;
        }
    }
    __syncthreads();

    // phase 3: D = agg @ W (3xTF32), C[64,200] per block
    int warp = tid >> 5;
    int lane = tid & 31;
    int m0 = warp * 16;
    int gr = lane >> 2;   // group id
    int tg = lane & 3;    // thread in group

    float c[NT][4];
#pragma unroll
    for (int nt = 0; nt < NT; nt++) {
        c[nt][0] = 0.f; c[nt][1] = 0.f; c[nt][2] = 0.f; c[nt][3] = 0.f;
    }

    const uint4* bpl = g_Bpack + (size_t)layer * KT * NT * 32 + lane;
    for (int kt = 0; kt < KT; kt++) {
        int k0 = kt * 8 + tg;
        float a0f = s_agg[(m0 + gr) * AGG_S + k0];
        float a1f = s_agg[(m0 + gr + 8) * AGG_S + k0];
        float a2f = s_agg[(m0 + gr) * AGG_S + k0 + 4];
        float a3f = s_agg[(m0 + gr + 8) * AGG_S + k0 + 4];
        uint32_t ahi[4], alo[4];
        ahi[0] = f2tf32(a0f); alo[0] = f2tf32(a0f - __uint_as_float(ahi[0]));
        ahi[1] = f2tf32(a1f); alo[1] = f2tf32(a1f - __uint_as_float(ahi[1]));
        ahi[2] = f2tf32(a2f); alo[2] = f2tf32(a2f - __uint_as_float(ahi[2]));
        ahi[3] = f2tf32(a3f); alo[3] = f2tf32(a3f - __uint_as_float(ahi[3]));
        const uint4* bp = bpl + (size_t)kt * NT * 32;
#pragma unroll
        for (int nt = 0; nt < NT; nt++) {
            uint4 p = __ldg(&bp[nt * 32]);
            mma_tf32(c[nt], ahi, p.x, p.y);   // Ahi*Bhi
            mma_tf32(c[nt], ahi, p.z, p.w);   // Ahi*Blo
            mma_tf32(c[nt], alo, p.x, p.y);   // Alo*Bhi
        }
    }

    // phase 4: h = relu(D + bias) + h_old
    {
        int r0 = m0 + gr;
        int r1 = r0 + 8;
#pragma unroll
        for (int nt = 0; nt < NT; nt++) {
            int n0 = nt * 8 + tg * 2;
            float b0v = s_bias[n0], b1v = s_bias[n0 + 1];
            float o00 = fmaxf(c[nt][0] + b0v, 0.f) + s_h[r0 * H + n0];
            float o01 = fmaxf(c[nt][1] + b1v, 0.f) + s_h[r0 * H + n0 + 1];
            float o10 = fmaxf(c[nt][2] + b0v, 0.f) + s_h[r1 * H + n0];
            float o11 = fmaxf(c[nt][3] + b1v, 0.f) + s_h[r1 * H + n0 + 1];
            *(float2*)(g_h + (size_t)(vbase + r0) * H + n0) = make_float2(o00, o01);
            *(float2*)(g_h + (size_t)(vbase + r1) * H + n0) = make_float2(o10, o11);
        }
    }
}

// ---------------- gf init ----------------
__global__ __launch_bounds__(200) void k_gf() {
    int g = blockIdx.x, c = threadIdx.x;
    float sum = 0.f;
    int base = g * NPG * H + c;
    for (int i = 0; i < NPG; i++) sum += g_h[base + i * H];
    g_gf[g * H + c] = sum;
}

// ---------------- readout attention ----------------
__global__ __launch_bounds__(256) void k_z(const float* __restrict__ lgW,
                                           const float* __restrict__ lgb, int t) {
    const float* w = lgW + t * H2;
    float bb = __ldg(&lgb[t]);
    int g = blockIdx.x;
    int tid = threadIdx.x;
    __shared__ float red[256];
    __shared__ float zs[NPG];

    float p = 0.f;
    if (tid < H) {
        float gfv = g_gf[g * H + tid];
        gfv = gfv > 0.f ? gfv : 0.f;
        p = gfv * w[tid];
    }
    red[tid] = p;
    __syncthreads();
    for (int off = 128; off > 0; off >>= 1) {
        if (tid < off) red[tid] += red[tid + off];
        __syncthreads();
    }
    float sg = red[0];

    int warp = tid >> 5, lane = tid & 31;
    for (int n = warp; n < NPG; n += 8) {
        int v = g * NPG + n;
        float sum = 0.f;
        for (int c = lane; c < H; c += 32) sum += g_h[v * H + c] * w[H + c];
        for (int off = 16; off; off >>= 1) sum += __shfl_xor_sync(0xffffffffu, sum, off);
        if (lane == 0) {
            float z = sum + sg + bb;
            zs[n] = z > 0.f ? z : 0.01f * z;
        }
    }
    __syncthreads();
    if (tid < 32) {
        float zv = zs[tid];
        float mx = zv;
        for (int off = 16; off; off >>= 1) mx = fmaxf(mx, __shfl_xor_sync(0xffffffffu, mx, off));
        float e = __expf(zv - mx);
        float den = e;
        for (int off = 16; off; off >>= 1) den += __shfl_xor_sync(0xffffffffu, den, off);
        g_a[g * NPG + tid] = e / den;
    }
}

// ---------------- hbar ----------------
__global__ __launch_bounds__(200) void k_hbar() {
    int g = blockIdx.x, c = threadIdx.x;
    float sum = 0.f;
    int vb = g * NPG;
    for (int i = 0; i < NPG; i++) sum += __ldg(&g_a[vb + i]) * g_h[(vb + i) * H + c];
    g_hbar[g * H + c] = sum;
}

// ---------------- ctx ----------------
__global__ __launch_bounds__(200) void k_ctx(const float* __restrict__ prW,
                                             const float* __restrict__ prb, int t) {
    const float* W = prW + t * H * H;
    const float* b = prb + t * H;
    __shared__ __align__(16) float s[32][H];
    int g0 = blockIdx.x * 32;
    int tid = threadIdx.x;
    for (int i = tid; i < 32 * H; i += 200) {
        int r = i / H, k = i - r * H;
        s[r][k] = g_hbar[(g0 + r) * H + k];
    }
    __syncthreads();
    int c = tid;
    float acc[32];
#pragma unroll
    for (int r = 0; r < 32; r++) acc[r] = 0.f;
    for (int k = 0; k < H; k += 4) {
        float w0 = W[k * H + c];
        float w1 = W[(k + 1) * H + c];
        float w2 = W[(k + 2) * H + c];
        float w3 = W[(k + 3) * H + c];
#pragma unroll
        for (int r = 0; r < 32; r++) {
            float4 a = *(const float4*)&s[r][k];
            acc[r] += a.x * w0 + a.y * w1 + a.z * w2 + a.w * w3;
        }
    }
    float bb = b[c];
#pragma unroll
    for (int r = 0; r < 32; r++) {
        float o = acc[r] + bb;
        o = o > 0.f ? o : expm1f(o);
        g_ctx[(g0 + r) * H + c] = o;
    }
}

// ---------------- GRU gate GEMMs ----------------
__global__ __launch_bounds__(600) void k_gru(const float* __restrict__ bih,
                                             const float* __restrict__ bhh, int t) {
    __shared__ __align__(16) float sc[16][H];
    __shared__ __align__(16) float sh[16][H];
    int g0 = blockIdx.x * 16;
    int tid = threadIdx.x;
    for (int i = tid; i < 16 * H; i += 600) {
        int r = i / H, k = i - r * H;
        sc[r][k] = g_ctx[(g0 + r) * H + k];
        sh[r][k] = g_gf[(g0 + r) * H + k];
    }
    __syncthreads();
    int j = tid;
    const float* Wi = g_WihT[t];
    const float* Wh = g_WhhT[t];
    float ai[16], ah[16];
#pragma unroll
    for (int r = 0; r < 16; r++) { ai[r] = 0.f; ah[r] = 0.f; }
    for (int k = 0; k < H; k += 4) {
        float wi0 = Wi[k * H3 + j], wi1 = Wi[(k + 1) * H3 + j];
        float wi2 = Wi[(k + 2) * H3 + j], wi3 = Wi[(k + 3) * H3 + j];
        float wh0 = Wh[k * H3 + j], wh1 = Wh[(k + 1) * H3 + j];
        float wh2 = Wh[(k + 2) * H3 + j], wh3 = Wh[(k + 3) * H3 + j];
#pragma unroll
        for (int r = 0; r < 16; r++) {
            float4 a = *(const float4*)&sc[r][k];
            ai[r] += a.x * wi0 + a.y * wi1 + a.z * wi2 + a.w * wi3;
            float4 h4 = *(const float4*)&sh[r][k];
            ah[r] += h4.x * wh0 + h4.y * wh1 + h4.z * wh2 + h4.w * wh3;
        }
    }
    float bi = bih[t * H3 + j], bh = bhh[t * H3 + j];
#pragma unroll
    for (int r = 0; r < 16; r++) {
        g_gi[(g0 + r) * H3 + j] = ai[r] + bi;
        g_gh[(g0 + r) * H3 + j] = ah[r] + bh;
    }
}

// ---------------- GRU combine ----------------
__global__ __launch_bounds__(200) void k_gate() {
    int g = blockIdx.x, c = threadIdx.x;
    int base = g * H3;
    float ir = g_gi[base + c],          hr = g_gh[base + c];
    float iz = g_gi[base + H + c],      hz = g_gh[base + H + c];
    float in_ = g_gi[base + 2 * H + c], hn = g_gh[base + 2 * H + c];
    float r = 1.f / (1.f + expf(-(ir + hr)));
    float u = 1.f / (1.f + expf(-(iz + hz)));
    float n = tanhf(in_ + r * hn);
    int o = g * H + c;
    g_gf[o] = (1.f - u) * n + u * g_gf[o];
}

// ---------------- copy result ----------------
__global__ void k_copy(float* __restrict__ out, int n) {
    int i = blockIdx.x * blockDim.x + threadIdx.x;
    if (i < n) out[i] = g_gf[i];
}

// ---------------- launcher ----------------
extern "C" void kernel_launch(void* const* d_in, const int* in_sizes, int n_in,
                              void* d_out, int out_size) {
    const float* node_feat = (const float*)d_in[0];
    const float* edge_feat = (const float*)d_in[1];
    const int*   src       = (const int*)d_in[2];
    const float* node_W = (const float*)d_in[5];
    const float* node_b = (const float*)d_in[6];
    const float* edge_W = (const float*)d_in[7];
    const float* edge_b = (const float*)d_in[8];
    const float* gnn_W  = (const float*)d_in[9];
    const float* gnn_b  = (const float*)d_in[10];
    const float* lg_W   = (const float*)d_in[11];
    const float* lg_b   = (const float*)d_in[12];
    const float* pr_W   = (const float*)d_in[13];
    const float* pr_b   = (const float*)d_in[14];
    const float* W_ih   = (const float*)d_in[15];
    const float* W_hh   = (const float*)d_in[16];
    const float* b_ih   = (const float*)d_in[17];
    const float* b_hh   = (const float*)d_in[18];

    const int SMEM_LAYER = (MB * H + MB * AGG_S + MB * DEG + H) * 4;
    cudaFuncSetAttribute(k_layer, cudaFuncAttributeMaxDynamicSharedMemorySize, SMEM_LAYER);

    k_prep<<<(NLAYERS * KT * NT * 32 + 255) / 256, 256>>>(gnn_W);
    k_transpose<<<(TT * H3 * H + 255) / 256, 256>>>(W_ih, W_hh);
    k_node_embed<<<Vn / 32, 200>>>(node_feat, node_W, node_b);
    k_edge_embed<<<En / 32, 200>>>(edge_feat, edge_W, edge_b);

    for (int i = 0; i < NLAYERS; i++) {
        k_layer<<<Vn / MB, 128, SMEM_LAYER>>>(src, gnn_b + i * H, i);
    }

    k_gf<<<Gn, 200>>>();
    for (int t = 0; t < TT; t++) {
        k_z<<<Gn, 256>>>(lg_W, lg_b, t);
        k_hbar<<<Gn, 200>>>();
        k_ctx<<<Gn / 32, 200>>>(pr_W, pr_b, t);
        k_gru<<<Gn / 16, 600>>>(b_ih, b_hh, t);
        k_gate<<<Gn, 200>>>();
    }

    k_copy<<<(Gn * H + 255) / 256, 256>>>((float*)d_out, Gn * H);
}